// round 4
// baseline (speedup 1.0000x reference)
#include <cuda_runtime.h>

// ---------------- problem constants ----------------
#define NZ     300
#define NX     400
#define NPML   32
#define NZP    (NZ + 2*NPML)            // 364
#define NXP    (NX + 2*NPML)            // 464
#define NXPP   480                      // global row pitch (floats)
#define NSTEPS 200
#define NSHOTS 2
#define DXC    0.01f
#define DTC    0.001f
#define SRC_Z  (NPML + 2)               // 34
#define REC_Z  (NPML + 2)               // 34

#define FSZ (NZP * NXPP)

#define BLKS_PER_SHOT 74
#define NBLK   (NSHOTS * BLKS_PER_SHOT) // 148
#define NTHR   1024
#define MAXC   3                        // max cells/thread: 5*464/1024 -> 3

// smem tile: rows 0..SROWS-1, row r <-> global row z0-1+r
#define SROWS  7                        // max nrows(5) + 2 halo
#define SPITCH 480
#define FTILE  (SROWS * SPITCH)         // floats per field tile
#define SMEM_DYN (5 * FTILE * 4)        // 67200 bytes

// flag bits
#define F_VAL 1
#define F_REC 2
#define F_SRC 4
#define F_TOP 8      // r == 1      (first owned row)
#define F_BOT 16     // r == nrows  (last owned row)
#define F_JP  32     // j > 0

// ---------------- device state (static, no allocs) ----------------
// global arrays used ONLY for boundary-row exchange (sxx never exchanged)
__device__ float g_vx [NSHOTS][FSZ];
__device__ float g_vz [NSHOTS][FSZ];
__device__ float g_szz[NSHOTS][FSZ];
__device__ float g_sxz[NSHOTS][FSZ];

__device__ unsigned g_flags[NBLK * 32];   // one flag per block, 128B apart
__device__ double   g_part[NBLK];
__device__ unsigned g_done = 0u;

// Publish own phase, wait for neighbors to reach it. Monotonic -> replay-safe.
__device__ __forceinline__ void sync_neighbors(int b, int nb_lo, int nb_hi, unsigned q)
{
    __syncthreads();
    if (threadIdx.x == 0) {
        __threadfence();
        *(volatile unsigned*)&g_flags[b * 32] = q;
        if (nb_lo >= 0) {
            volatile unsigned* f = &g_flags[nb_lo * 32];
            while ((int)(*f - q) < 0) { }
        }
    }
    if (threadIdx.x == 1 && nb_hi >= 0) {
        volatile unsigned* f = &g_flags[nb_hi * 32];
        while ((int)(*f - q) < 0) { }
    }
    if (threadIdx.x < 2) __threadfence();
    __syncthreads();
}

__global__ void __launch_bounds__(NTHR, 1)
fwi_persistent(const float* __restrict__ Vp,
               const float* __restrict__ Vs,
               const float* __restrict__ Den,
               const float* __restrict__ Stf,
               const float* __restrict__ Mask,
               const int*   __restrict__ ShotIds,
               float*       __restrict__ out)
{
    extern __shared__ float sm[];
    float* __restrict__ s_vx  = sm;
    float* __restrict__ s_vz  = sm + 1 * FTILE;
    float* __restrict__ s_sxx = sm + 2 * FTILE;
    float* __restrict__ s_szz = sm + 3 * FTILE;
    float* __restrict__ s_sxz = sm + 4 * FTILE;

    const int b   = blockIdx.x;
    const int s   = b / BLKS_PER_SHOT;
    const int kk  = b - s * BLKS_PER_SHOT;
    const int z0  = (kk * NZP) / BLKS_PER_SHOT;
    const int z1  = ((kk + 1) * NZP) / BLKS_PER_SHOT;
    const int nrows  = z1 - z0;
    const int ncells = nrows * NXP;
    const int tid = threadIdx.x;

    const int nb_lo = (kk > 0)                 ? b - 1 : -1;
    const int nb_hi = (kk < BLKS_PER_SHOT - 1) ? b + 1 : -1;

    float* __restrict__ vxg  = g_vx [s];
    float* __restrict__ vzg  = g_vz [s];
    float* __restrict__ szzg = g_szz[s];
    float* __restrict__ sxzg = g_sxz[s];

    const float inv_dx = 1.0f / DXC;

    unsigned q = *(volatile unsigned*)&g_flags[b * 32];

    // ---------- prep: zero smem tiles + own global exchange rows ----------
    for (int c = tid; c < 5 * FTILE; c += NTHR) sm[c] = 0.0f;
    for (int c = tid; c < nrows * NXPP; c += NTHR) {
        int rem = z0 * NXPP + c;
        vxg[rem] = 0.0f; vzg[rem] = 0.0f; szzg[rem] = 0.0f; sxzg[rem] = 0.0f;
    }

    // ---------- per-thread cells: smem offset, global offset, coeffs ----------
    int   soff[MAXC], goff[MAXC], fl[MAXC];
    float cdamp[MAXC], cdtrho[MAXC], clam[MAXC], cl2mu[MAXC], cmu[MAXC];

    const int sid  = ShotIds[s];
    const int srcx = NPML + 20 + sid * ((NX - 40) / NSHOTS);
    const float* stf = Stf + sid * NSTEPS;

    #pragma unroll
    for (int k = 0; k < MAXC; ++k) {
        int c  = tid + k * NTHR;
        int v  = (c < ncells);
        int cc = v ? c : 0;
        int r  = cc / NXP + 1;              // smem row 1..nrows
        int j  = cc - (r - 1) * NXP;
        int i  = z0 - 1 + r;                // global row

        soff[k] = r * SPITCH + j;
        goff[k] = i * NXPP + j;

        int f = v ? F_VAL : 0;
        if (v && i == REC_Z && j >= NPML && j < NPML + NX) f |= F_REC;
        if (v && i == SRC_Z && j == srcx)                  f |= F_SRC;
        if (r == 1)      f |= F_TOP;
        if (r == nrows)  f |= F_BOT;
        if (j > 0)       f |= F_JP;
        fl[k] = f;

        int ip = min(max(i - NPML, 0), NZ - 1);
        int jp = min(max(j - NPML, 0), NX - 1);
        float vp  = Vp [ip * NX + jp];
        float vs  = Vs [ip * NX + jp];
        float den = Den[ip * NX + jp];
        float m   = Mask[i * NXP + j];
        vp  = m * vp  + (1.0f - m) * vp;
        vs  = m * vs  + (1.0f - m) * vs;
        den = m * den + (1.0f - m) * den;

        float mu  = vs * vs * den * 1e-6f;
        float lam = (vp * vp - 2.0f * vs * vs) * den * 1e-6f;
        cmu[k]    = mu;
        clam[k]   = lam;
        cl2mu[k]  = lam + 2.0f * mu;
        cdtrho[k] = DTC / den;

        float a1 = (float)(NPML - i);
        float a2 = (float)(i - (NZP - 1 - NPML));
        float dz = fmaxf(a1, a2); dz = fminf(fmaxf(dz, 0.0f), (float)NPML) / (float)NPML;
        float b1 = (float)(NPML - j);
        float b2 = (float)(j - (NXP - 1 - NPML));
        float dxs = fmaxf(b1, b2); dxs = fminf(fmaxf(dxs, 0.0f), (float)NPML) / (float)NPML;
        cdamp[k] = expf(-0.1f * (dz * dz + dxs * dxs));
    }

    ++q;
    sync_neighbors(b, nb_lo, nb_hi, q);   // prep visible everywhere

    double acc = 0.0;

    const int haloT = 0;                   // smem row for global row z0-1
    const int haloB = (nrows + 1) * SPITCH;// smem row for global row z1

    // ---------------- time loop ----------------
    for (int t = 0; t < NSTEPS; ++t) {
        // ---- import stress halos (published by neighbors' previous stress phase) ----
        if (tid < NXP) {
            s_sxz[haloT + tid] = (z0 > 0)   ? __ldcg(&sxzg[(z0 - 1) * NXPP + tid]) : 0.0f;
            s_szz[haloB + tid] = (z1 < NZP) ? __ldcg(&szzg[ z1      * NXPP + tid]) : 0.0f;
        }
        __syncthreads();

        // ---- velocity half-step ----
        #pragma unroll
        for (int k = 0; k < MAXC; ++k) {
            const int f = fl[k];
            if (!(f & F_VAL)) continue;
            const int so = soff[k];

            float sxx_c = s_sxx[so];
            float sxx_r = s_sxx[so + 1];
            float sxz_c = s_sxz[so];
            float sxz_u = s_sxz[so - SPITCH];
            float sxz_l = (f & F_JP) ? s_sxz[so - 1] : 0.0f;
            float szz_c = s_szz[so];
            float szz_d = s_szz[so + SPITCH];

            float nvx = (s_vx[so] + cdtrho[k] * ((sxx_r - sxx_c) + (sxz_c - sxz_u)) * inv_dx) * cdamp[k];
            float nvz = (s_vz[so] + cdtrho[k] * ((sxz_c - sxz_l) + (szz_d - szz_c)) * inv_dx) * cdamp[k];

            s_vx[so] = nvx;
            s_vz[so] = nvz;

            if (f & F_TOP) __stcg(&vxg[goff[k]], nvx);   // row z0   -> lo neighbor
            if (f & F_BOT) __stcg(&vzg[goff[k]], nvz);   // row z1-1 -> hi neighbor

            if (f & F_REC) acc += (double)nvx * (double)nvx;
        }

        ++q;
        sync_neighbors(b, nb_lo, nb_hi, q);

        // ---- import velocity halos ----
        if (tid < NXP) {
            s_vz[haloT + tid] = (z0 > 0)   ? __ldcg(&vzg[(z0 - 1) * NXPP + tid]) : 0.0f;
            s_vx[haloB + tid] = (z1 < NZP) ? __ldcg(&vxg[ z1      * NXPP + tid]) : 0.0f;
        }
        __syncthreads();

        // ---- stress half-step ----
        #pragma unroll
        for (int k = 0; k < MAXC; ++k) {
            const int f = fl[k];
            if (!(f & F_VAL)) continue;
            const int so = soff[k];

            float vx_c = s_vx[so];
            float vx_l = (f & F_JP) ? s_vx[so - 1] : 0.0f;
            float vx_d = s_vx[so + SPITCH];
            float vz_c = s_vz[so];
            float vz_u = s_vz[so - SPITCH];
            float vz_r = s_vz[so + 1];

            float dvxdx = (vx_c - vx_l) * inv_dx;
            float dvzdz = (vz_c - vz_u) * inv_dx;

            float sxxn = (s_sxx[so] + DTC * (cl2mu[k] * dvxdx + clam[k]  * dvzdz)) * cdamp[k];
            float szzn = (s_szz[so] + DTC * (clam[k]  * dvxdx + cl2mu[k] * dvzdz)) * cdamp[k];
            float sxzn = (s_sxz[so] + DTC * cmu[k] * ((vx_d - vx_c) + (vz_r - vz_c)) * inv_dx) * cdamp[k];

            if (f & F_SRC) {
                float sv = stf[t] * DTC;
                sxxn += sv;
                szzn += sv;
            }

            s_sxx[so] = sxxn;
            s_szz[so] = szzn;
            s_sxz[so] = sxzn;

            if (f & F_BOT) __stcg(&sxzg[goff[k]], sxzn);  // row z1-1 -> hi neighbor
            if (f & F_TOP) __stcg(&szzg[goff[k]], szzn);  // row z0   -> lo neighbor
        }

        ++q;
        sync_neighbors(b, nb_lo, nb_hi, q);
    }

    // ---------------- deterministic reduction ----------------
    __shared__ double sh[NTHR];
    sh[tid] = acc;
    __syncthreads();
    for (int o = NTHR / 2; o > 0; o >>= 1) {
        if (tid < o) sh[tid] += sh[tid + o];
        __syncthreads();
    }

    __shared__ int is_last;
    if (tid == 0) {
        g_part[b] = sh[0];
        __threadfence();
        unsigned ticket = atomicAdd(&g_done, 1u);
        is_last = ((ticket + 1u) % NBLK == 0u) ? 1 : 0;
    }
    __syncthreads();

    if (is_last) {
        __threadfence();
        double a = 0.0;
        if (tid < NBLK) a = __ldcg(&g_part[tid]);
        sh[tid] = a;
        __syncthreads();
        for (int o = NTHR / 2; o > 0; o >>= 1) {
            if (tid < o) sh[tid] += sh[tid + o];
            __syncthreads();
        }
        if (tid == 0) out[0] = (float)(0.5 * sh[0]);
    }
}

// ---------------- launcher ----------------
extern "C" void kernel_launch(void* const* d_in, const int* in_sizes, int n_in,
                              void* d_out, int out_size)
{
    const float* Vp      = (const float*)d_in[0];
    const float* Vs      = (const float*)d_in[1];
    const float* Den     = (const float*)d_in[2];
    const float* Stf     = (const float*)d_in[3];
    const float* Mask    = (const float*)d_in[4];
    const int*   ShotIds = (const int*)  d_in[5];
    float*       out     = (float*)d_out;
    (void)in_sizes; (void)n_in; (void)out_size;

    static int smem_set = 0;
    if (!smem_set) {
        cudaFuncSetAttribute(fwi_persistent,
                             cudaFuncAttributeMaxDynamicSharedMemorySize, SMEM_DYN);
        smem_set = 1;
    }

    fwi_persistent<<<NBLK, NTHR, SMEM_DYN>>>(Vp, Vs, Den, Stf, Mask, ShotIds, out);
}

// round 5
// speedup vs baseline: 1.7659x; 1.7659x over previous
#include <cuda_runtime.h>

// ---------------- problem constants ----------------
#define NZ     300
#define NX     400
#define NPML   32
#define NZP    (NZ + 2*NPML)            // 364
#define NXP    (NX + 2*NPML)            // 464
#define NXPP   480                      // global row pitch (floats)
#define NSTEPS 200
#define NSHOTS 2
#define DXC    0.01f
#define DTC    0.001f
#define SRC_Z  (NPML + 2)               // 34
#define REC_Z  (NPML + 2)               // 34

#define FSZ (NZP * NXPP)

#define BLKS_PER_SHOT 74
#define NBLK   (NSHOTS * BLKS_PER_SHOT) // 148
#define NTHR   1024
#define MAXC   3                        // max cells/thread (5*464/1024 -> 3)

// smem tile: row r <-> global row z0-1+r (r=0 top halo, r=nrows+1 bottom halo)
#define SROWS  7
#define SPITCH 480
#define FTILE  (SROWS * SPITCH)
#define SMEM_DYN (5 * FTILE * 4)        // 67200 B

// flag bits
#define F_VAL 1
#define F_REC 2
#define F_SRC 4
#define F_TOP 8      // r == 1     (first owned row)  -> publish to lo
#define F_BOT 16     // r == nrows (last owned row)   -> publish to hi
#define F_JP  32     // j > 0

// ---------------- device state (static, no allocs) ----------------
// global arrays used ONLY for boundary-row exchange (flag-gated; never stale-read)
__device__ float g_vx [NSHOTS][FSZ];
__device__ float g_vz [NSHOTS][FSZ];
__device__ float g_szz[NSHOTS][FSZ];
__device__ float g_sxz[NSHOTS][FSZ];

__device__ unsigned g_flags[NBLK * 32];   // one flag per block, 128B apart (monotonic)
__device__ double   g_part[NBLK];
__device__ unsigned g_done = 0u;

// ---------------- scoped sync primitives ----------------
__device__ __forceinline__ void st_release_u32(unsigned* p, unsigned v)
{
    asm volatile("st.release.gpu.global.u32 [%0], %1;" :: "l"(p), "r"(v) : "memory");
}
__device__ __forceinline__ unsigned ld_acquire_u32(const unsigned* p)
{
    unsigned v;
    asm volatile("ld.acquire.gpu.global.u32 %0, [%1];" : "=r"(v) : "l"(p) : "memory");
    return v;
}
__device__ __forceinline__ void wait_flag(const unsigned* f, unsigned q)
{
    while ((int)(ld_acquire_u32(f) - q) < 0) { }
}

__global__ void __launch_bounds__(NTHR, 1)
fwi_persistent(const float* __restrict__ Vp,
               const float* __restrict__ Vs,
               const float* __restrict__ Den,
               const float* __restrict__ Stf,
               const float* __restrict__ Mask,
               const int*   __restrict__ ShotIds,
               float*       __restrict__ out)
{
    extern __shared__ float sm[];
    float* __restrict__ s_vx  = sm;
    float* __restrict__ s_vz  = sm + 1 * FTILE;
    float* __restrict__ s_sxx = sm + 2 * FTILE;
    float* __restrict__ s_szz = sm + 3 * FTILE;
    float* __restrict__ s_sxz = sm + 4 * FTILE;

    const int b   = blockIdx.x;
    const int s   = b / BLKS_PER_SHOT;
    const int kk  = b - s * BLKS_PER_SHOT;
    const int z0  = (kk * NZP) / BLKS_PER_SHOT;
    const int z1  = ((kk + 1) * NZP) / BLKS_PER_SHOT;
    const int nrows  = z1 - z0;
    const int ncells = nrows * NXP;
    const int tid = threadIdx.x;

    const int nb_lo = (kk > 0)                 ? b - 1 : -1;
    const int nb_hi = (kk < BLKS_PER_SHOT - 1) ? b + 1 : -1;

    float* __restrict__ vxg  = g_vx [s];
    float* __restrict__ vzg  = g_vz [s];
    float* __restrict__ szzg = g_szz[s];
    float* __restrict__ sxzg = g_sxz[s];

    const float inv_dx = 1.0f / DXC;

    unsigned q = *(volatile unsigned*)&g_flags[b * 32];   // monotonic base (replay-safe)
    unsigned* myflag = &g_flags[b * 32];

    // ---------- prep: zero smem tiles (halos included) ----------
    for (int c = tid; c < 5 * FTILE; c += NTHR) sm[c] = 0.0f;

    // ---------- per-thread cells (BOUNDARY ROWS FIRST), coeffs in registers ----------
    // c < NXP           : r = 1        (top owned row)
    // NXP <= c < 2*NXP  : r = nrows    (bottom owned row)
    // c >= 2*NXP        : interior rows 2..nrows-1
    int   soff[MAXC], goff[MAXC], fl[MAXC];
    float cdamp[MAXC], cdtrho[MAXC], clam[MAXC], cl2mu[MAXC], cmu[MAXC];

    const int sid  = ShotIds[s];
    const int srcx = NPML + 20 + sid * ((NX - 40) / NSHOTS);
    const float* stf = Stf + sid * NSTEPS;

    #pragma unroll
    for (int k = 0; k < MAXC; ++k) {
        int c  = tid + k * NTHR;
        int v  = (c < ncells);
        int cc = v ? c : 0;
        int r, j;
        if (cc < NXP)            { r = 1;                      j = cc; }
        else if (cc < 2 * NXP)   { r = nrows;                  j = cc - NXP; }
        else { int ci2 = cc - 2 * NXP; r = 2 + ci2 / NXP;      j = ci2 - (ci2 / NXP) * NXP; }
        int i = z0 - 1 + r;

        soff[k] = r * SPITCH + j;
        goff[k] = i * NXPP + j;

        int f = v ? F_VAL : 0;
        if (v && i == REC_Z && j >= NPML && j < NPML + NX) f |= F_REC;
        if (v && i == SRC_Z && j == srcx)                  f |= F_SRC;
        if (v && r == 1)      f |= F_TOP;
        if (v && r == nrows)  f |= F_BOT;
        if (j > 0)            f |= F_JP;
        fl[k] = f;

        int ip = min(max(i - NPML, 0), NZ - 1);
        int jp = min(max(j - NPML, 0), NX - 1);
        float vp  = Vp [ip * NX + jp];
        float vs  = Vs [ip * NX + jp];
        float den = Den[ip * NX + jp];
        float m   = Mask[i * NXP + j];
        vp  = m * vp  + (1.0f - m) * vp;
        vs  = m * vs  + (1.0f - m) * vs;
        den = m * den + (1.0f - m) * den;

        float mu  = vs * vs * den * 1e-6f;
        float lam = (vp * vp - 2.0f * vs * vs) * den * 1e-6f;
        cmu[k]    = mu;
        clam[k]   = lam;
        cl2mu[k]  = lam + 2.0f * mu;
        cdtrho[k] = DTC / den;

        float a1 = (float)(NPML - i);
        float a2 = (float)(i - (NZP - 1 - NPML));
        float dz = fmaxf(a1, a2); dz = fminf(fmaxf(dz, 0.0f), (float)NPML) / (float)NPML;
        float b1 = (float)(NPML - j);
        float b2 = (float)(j - (NXP - 1 - NPML));
        float dxs = fmaxf(b1, b2); dxs = fminf(fmaxf(dxs, 0.0f), (float)NPML) / (float)NPML;
        cdamp[k] = expf(-0.1f * (dz * dz + dxs * dxs));
    }

    __syncthreads();   // smem zero + coeffs ready (block-local; no global sync needed)

    double acc = 0.0;

    const int haloT = 0;
    const int haloB = (nrows + 1) * SPITCH;

    // ---- per-cell compute bodies ----
    auto vcell = [&](int k) {
        const int f = fl[k];
        if (!(f & F_VAL)) return;
        const int so = soff[k];

        float sxx_c = s_sxx[so];
        float sxx_r = s_sxx[so + 1];
        float sxz_c = s_sxz[so];
        float sxz_u = s_sxz[so - SPITCH];
        float sxz_l = (f & F_JP) ? s_sxz[so - 1] : 0.0f;
        float szz_c = s_szz[so];
        float szz_d = s_szz[so + SPITCH];

        float nvx = (s_vx[so] + cdtrho[k] * ((sxx_r - sxx_c) + (sxz_c - sxz_u)) * inv_dx) * cdamp[k];
        float nvz = (s_vz[so] + cdtrho[k] * ((sxz_c - sxz_l) + (szz_d - szz_c)) * inv_dx) * cdamp[k];

        s_vx[so] = nvx;
        s_vz[so] = nvz;

        if (f & F_TOP) __stcg(&vxg[goff[k]], nvx);   // lo neighbor's vx(i+1)
        if (f & F_BOT) __stcg(&vzg[goff[k]], nvz);   // hi neighbor's vz(i-1)
        if (f & F_REC) acc += (double)nvx * (double)nvx;
    };

    auto scell = [&](int k, int t) {
        const int f = fl[k];
        if (!(f & F_VAL)) return;
        const int so = soff[k];

        float vx_c = s_vx[so];
        float vx_l = (f & F_JP) ? s_vx[so - 1] : 0.0f;
        float vx_d = s_vx[so + SPITCH];
        float vz_c = s_vz[so];
        float vz_u = s_vz[so - SPITCH];
        float vz_r = s_vz[so + 1];

        float dvxdx = (vx_c - vx_l) * inv_dx;
        float dvzdz = (vz_c - vz_u) * inv_dx;

        float sxxn = (s_sxx[so] + DTC * (cl2mu[k] * dvxdx + clam[k]  * dvzdz)) * cdamp[k];
        float szzn = (s_szz[so] + DTC * (clam[k]  * dvxdx + cl2mu[k] * dvzdz)) * cdamp[k];
        float sxzn = (s_sxz[so] + DTC * cmu[k] * ((vx_d - vx_c) + (vz_r - vz_c)) * inv_dx) * cdamp[k];

        if (f & F_SRC) {
            float sv = stf[t] * DTC;
            sxxn += sv;
            szzn += sv;
        }

        s_sxx[so] = sxxn;
        s_szz[so] = szzn;
        s_sxz[so] = sxzn;

        if (f & F_TOP) __stcg(&szzg[goff[k]], szzn);  // lo neighbor's szz(i+1)
        if (f & F_BOT) __stcg(&sxzg[goff[k]], sxzn);  // hi neighbor's sxz(i-1)
    };

    // ---------------- time loop ----------------
    for (int t = 0; t < NSTEPS; ++t) {
        // ===== velocity half-step =====
        vcell(0);                               // all boundary cells live in chunk 0
        __syncthreads();                        // boundary stores done (smem + stcg)
        ++q;
        if (tid == 0) st_release_u32(myflag, q);  // publish V(t)
        #pragma unroll
        for (int k = 1; k < MAXC; ++k) vcell(k);  // interior overlaps neighbor handshakes

        // import velocity halos for stress phase (flag almost surely already set)
        if (nb_lo >= 0 && tid < NXP) {
            wait_flag(&g_flags[nb_lo * 32], q);
            s_vz[haloT + tid] = __ldcg(&vzg[(z0 - 1) * NXPP + tid]);
        }
        if (nb_hi >= 0 && tid >= 512 && tid < 512 + NXP) {
            wait_flag(&g_flags[nb_hi * 32], q);
            s_vx[haloB + (tid - 512)] = __ldcg(&vxg[z1 * NXPP + (tid - 512)]);
        }
        __syncthreads();

        // ===== stress half-step =====
        scell(0, t);
        __syncthreads();
        ++q;
        if (tid == 0) st_release_u32(myflag, q);  // publish S(t)
        #pragma unroll
        for (int k = 1; k < MAXC; ++k) scell(k, t);

        // import stress halos for next velocity phase
        if (nb_lo >= 0 && tid < NXP) {
            wait_flag(&g_flags[nb_lo * 32], q);
            s_sxz[haloT + tid] = __ldcg(&sxzg[(z0 - 1) * NXPP + tid]);
        }
        if (nb_hi >= 0 && tid >= 512 && tid < 512 + NXP) {
            wait_flag(&g_flags[nb_hi * 32], q);
            s_szz[haloB + (tid - 512)] = __ldcg(&szzg[z1 * NXPP + (tid - 512)]);
        }
        __syncthreads();
    }

    // ---------------- deterministic reduction ----------------
    __shared__ double sh[NTHR];
    sh[tid] = acc;
    __syncthreads();
    for (int o = NTHR / 2; o > 0; o >>= 1) {
        if (tid < o) sh[tid] += sh[tid + o];
        __syncthreads();
    }

    __shared__ int is_last;
    if (tid == 0) {
        g_part[b] = sh[0];
        __threadfence();
        unsigned ticket = atomicAdd(&g_done, 1u);
        is_last = ((ticket + 1u) % NBLK == 0u) ? 1 : 0;
    }
    __syncthreads();

    if (is_last) {
        __threadfence();
        double a = 0.0;
        if (tid < NBLK) a = __ldcg(&g_part[tid]);
        sh[tid] = a;
        __syncthreads();
        for (int o = NTHR / 2; o > 0; o >>= 1) {
            if (tid < o) sh[tid] += sh[tid + o];
            __syncthreads();
        }
        if (tid == 0) out[0] = (float)(0.5 * sh[0]);
    }
}

// ---------------- launcher ----------------
extern "C" void kernel_launch(void* const* d_in, const int* in_sizes, int n_in,
                              void* d_out, int out_size)
{
    const float* Vp      = (const float*)d_in[0];
    const float* Vs      = (const float*)d_in[1];
    const float* Den     = (const float*)d_in[2];
    const float* Stf     = (const float*)d_in[3];
    const float* Mask    = (const float*)d_in[4];
    const int*   ShotIds = (const int*)  d_in[5];
    float*       out     = (float*)d_out;
    (void)in_sizes; (void)n_in; (void)out_size;

    static int smem_set = 0;
    if (!smem_set) {
        cudaFuncSetAttribute(fwi_persistent,
                             cudaFuncAttributeMaxDynamicSharedMemorySize, SMEM_DYN);
        smem_set = 1;
    }

    fwi_persistent<<<NBLK, NTHR, SMEM_DYN>>>(Vp, Vs, Den, Stf, Mask, ShotIds, out);
}